// round 4
// baseline (speedup 1.0000x reference)
#include <cuda_runtime.h>
#include <cstdint>

#define NNODES 100000
#define CH 128

// ---------------- scratch (static __device__ globals; no allocation) -------
__device__ __align__(16) float4 g_bufA[NNODES * 32];   // 100000 x 128 floats
__device__ __align__(16) float4 g_bufB[NNODES * 32];   // 100000 x 128 floats
__device__ __align__(16) float4 g_hw3 [NNODES * 10];   // 100000 x 40 floats
__device__ __align__(16) float4 g_agg3[NNODES * 10];   // 100000 x 40 floats
__device__ float g_deg [NNODES];
__device__ float g_dinv[NNODES];
__device__ float g_sums[512];                           // 2 layers x (sum[128], sumsq[128])
__device__ __align__(16) float g_scale[256];
__device__ __align__(16) float g_shift[256];
__device__ unsigned g_keys[4];                          // dk0.(x,y), dk1.(x,y)

// ---------------- threefry2x32 (JAX-exact, 20 rounds) ----------------------
__device__ __forceinline__ void tf_round(uint32_t &x0, uint32_t &x1, int r) {
    x0 += x1;
    x1 = __funnelshift_l(x1, x1, r);
    x1 ^= x0;
}

__device__ __forceinline__ uint2 tf_full(uint32_t k0, uint32_t k1, uint32_t x0, uint32_t x1) {
    uint32_t k2 = k0 ^ k1 ^ 0x1BD11BDAu;
    x0 += k0; x1 += k1;
    tf_round(x0,x1,13); tf_round(x0,x1,15); tf_round(x0,x1,26); tf_round(x0,x1,6);
    x0 += k1; x1 += k2 + 1u;
    tf_round(x0,x1,17); tf_round(x0,x1,29); tf_round(x0,x1,16); tf_round(x0,x1,24);
    x0 += k2; x1 += k0 + 2u;
    tf_round(x0,x1,13); tf_round(x0,x1,15); tf_round(x0,x1,26); tf_round(x0,x1,6);
    x0 += k0; x1 += k1 + 3u;
    tf_round(x0,x1,17); tf_round(x0,x1,29); tf_round(x0,x1,16); tf_round(x0,x1,24);
    x0 += k1; x1 += k2 + 4u;
    tf_round(x0,x1,13); tf_round(x0,x1,15); tf_round(x0,x1,26); tf_round(x0,x1,6);
    x0 += k2; x1 += k0 + 5u;
    return make_uint2(x0, x1);
}

// JAX partitionable random_bits(32): bits(i) = bits1 ^ bits2 of threefry(key,(0,i))
__device__ __forceinline__ uint32_t tf_bits_xor(uint32_t k0, uint32_t k1, uint32_t k2, uint32_t ctr) {
    uint32_t x0 = k0;          // 0 + ks0
    uint32_t x1 = ctr + k1;
    tf_round(x0,x1,13); tf_round(x0,x1,15); tf_round(x0,x1,26); tf_round(x0,x1,6);
    x0 += k1; x1 += k2 + 1u;
    tf_round(x0,x1,17); tf_round(x0,x1,29); tf_round(x0,x1,16); tf_round(x0,x1,24);
    x0 += k2; x1 += k0 + 2u;
    tf_round(x0,x1,13); tf_round(x0,x1,15); tf_round(x0,x1,26); tf_round(x0,x1,6);
    x0 += k0; x1 += k1 + 3u;
    tf_round(x0,x1,17); tf_round(x0,x1,29); tf_round(x0,x1,16); tf_round(x0,x1,24);
    x0 += k1; x1 += k2 + 4u;
    tf_round(x0,x1,13); tf_round(x0,x1,15); tf_round(x0,x1,26); tf_round(x0,x1,6);
    x0 += k2; x1 += k0 + 5u;
    return x0 ^ x1;            // <-- JAX partitionable 32-bit bits: XOR of both words
}

__global__ void k_keys() {
    if (threadIdx.x == 0) {
        // parent key(42) = (0, 42); foldlike split: child i = threefry(parent, (0, i))
        uint2 a = tf_full(0u, 42u, 0u, 0u);
        uint2 b = tf_full(0u, 42u, 0u, 1u);
        g_keys[0] = a.x; g_keys[1] = a.y;
        g_keys[2] = b.x; g_keys[3] = b.y;
    }
}

// ---------------- degree / dinv --------------------------------------------
__global__ void k_zero() {
    int i = blockIdx.x * 256 + threadIdx.x;
    if (i < NNODES) g_deg[i] = 0.f;
    if (i < 512)    g_sums[i] = 0.f;
}

__global__ void k_degree(const int* __restrict__ dst, int E) {
    int e = blockIdx.x * 256 + threadIdx.x;
    if (e < E) atomicAdd(&g_deg[dst[e]], 1.0f);
}

__global__ void k_dinv() {
    int i = blockIdx.x * 256 + threadIdx.x;
    if (i < NNODES) g_dinv[i] = rsqrtf(g_deg[i] + 1.0f);
}

// ---------------- SGEMM: C[M x NC] = A[M x 128] * B[128 x NC], NC <= 128 ---
__global__ __launch_bounds__(256) void sgemm_k128(
    const float* __restrict__ A, const float* __restrict__ B,
    float* __restrict__ C, int M, int NC)
{
    __shared__ __align__(16) float As[8][128];   // [k][row] (transposed)
    __shared__ __align__(16) float Bs[8][128];   // [k][col]
    int tid  = threadIdx.x;
    int row0 = blockIdx.x * 128;
    int tx = tid & 15, ty = tid >> 4;

    float acc[8][8];
#pragma unroll
    for (int i = 0; i < 8; i++)
#pragma unroll
        for (int j = 0; j < 8; j++) acc[i][j] = 0.f;

    int a_row = tid >> 1;
    int a_c4  = (tid & 1) * 4;
    int b_row = tid >> 5;
    int b_c4  = (tid & 31) * 4;

    for (int k0 = 0; k0 < 128; k0 += 8) {
        float4 av = make_float4(0.f, 0.f, 0.f, 0.f);
        int gr = row0 + a_row;
        if (gr < M) av = *(const float4*)(A + gr * 128 + k0 + a_c4);
        As[a_c4 + 0][a_row] = av.x;
        As[a_c4 + 1][a_row] = av.y;
        As[a_c4 + 2][a_row] = av.z;
        As[a_c4 + 3][a_row] = av.w;

        if (NC == 128) {
            *(float4*)&Bs[b_row][b_c4] = *(const float4*)(B + (k0 + b_row) * 128 + b_c4);
        } else {
#pragma unroll
            for (int j = 0; j < 4; j++) {
                int c = b_c4 + j;
                Bs[b_row][c] = (c < NC) ? B[(k0 + b_row) * NC + c] : 0.f;
            }
        }
        __syncthreads();

#pragma unroll
        for (int k = 0; k < 8; k++) {
            float af[8], bf[8];
            *(float4*)&af[0] = *(const float4*)&As[k][ty * 8];
            *(float4*)&af[4] = *(const float4*)&As[k][ty * 8 + 4];
            *(float4*)&bf[0] = *(const float4*)&Bs[k][tx * 8];
            *(float4*)&bf[4] = *(const float4*)&Bs[k][tx * 8 + 4];
#pragma unroll
            for (int i = 0; i < 8; i++)
#pragma unroll
                for (int j = 0; j < 8; j++)
                    acc[i][j] = fmaf(af[i], bf[j], acc[i][j]);
        }
        __syncthreads();
    }

    if (NC == 128) {
#pragma unroll
        for (int i = 0; i < 8; i++) {
            int r = row0 + ty * 8 + i;
            if (r < M) {
                *(float4*)(C + r * 128 + tx * 8)     = make_float4(acc[i][0], acc[i][1], acc[i][2], acc[i][3]);
                *(float4*)(C + r * 128 + tx * 8 + 4) = make_float4(acc[i][4], acc[i][5], acc[i][6], acc[i][7]);
            }
        }
    } else {
#pragma unroll
        for (int i = 0; i < 8; i++) {
            int r = row0 + ty * 8 + i;
            if (r < M) {
#pragma unroll
                for (int j = 0; j < 8; j++) {
                    int c = tx * 8 + j;
                    if (c < NC) C[r * NC + c] = acc[i][j];
                }
            }
        }
    }
}

// ---------------- self-loop init + bias ------------------------------------
__global__ void k_init128(const float4* __restrict__ hw, float4* __restrict__ agg,
                          const float* __restrict__ bias, int n4) {
    int t = blockIdx.x * 256 + threadIdx.x;
    if (t >= n4) return;
    float di = g_dinv[t >> 5];
    float di2 = di * di;
    float4 v = hw[t];
    float4 b = ((const float4*)bias)[t & 31];
    agg[t] = make_float4(fmaf(v.x, di2, b.x), fmaf(v.y, di2, b.y),
                         fmaf(v.z, di2, b.z), fmaf(v.w, di2, b.w));
}

__global__ void k_init40(const float4* __restrict__ hw, float4* __restrict__ agg,
                         const float* __restrict__ bias, int n4) {
    int t = blockIdx.x * 256 + threadIdx.x;
    if (t >= n4) return;
    int row = t / 10;
    int c4  = t - row * 10;
    float di = g_dinv[row];
    float di2 = di * di;
    float4 v = hw[t];
    float4 b = ((const float4*)bias)[c4];
    agg[t] = make_float4(fmaf(v.x, di2, b.x), fmaf(v.y, di2, b.y),
                         fmaf(v.z, di2, b.z), fmaf(v.w, di2, b.w));
}

// ---------------- edge scatter (warp per edge, vector red) -----------------
__global__ __launch_bounds__(256) void scatter128(
    const float4* __restrict__ hw, float4* __restrict__ agg,
    const int* __restrict__ src, const int* __restrict__ dst, int E)
{
    int e = blockIdx.x * 8 + (threadIdx.x >> 5);
    if (e >= E) return;
    int lane = threadIdx.x & 31;
    int s = __ldg(src + e);
    int d = __ldg(dst + e);
    float norm = __ldg(&g_dinv[s]) * __ldg(&g_dinv[d]);
    float4 v = __ldg(hw + s * 32 + lane);
    float4* p = agg + d * 32 + lane;
    asm volatile("red.global.add.v4.f32 [%0], {%1, %2, %3, %4};" ::
                 "l"(p), "f"(v.x * norm), "f"(v.y * norm),
                 "f"(v.z * norm), "f"(v.w * norm) : "memory");
}

__global__ __launch_bounds__(256) void scatter40(
    const float* __restrict__ hw, float* __restrict__ agg,
    const int* __restrict__ src, const int* __restrict__ dst, int E)
{
    int e = blockIdx.x * 8 + (threadIdx.x >> 5);
    if (e >= E) return;
    int lane = threadIdx.x & 31;
    int s = __ldg(src + e);
    int d = __ldg(dst + e);
    float norm = __ldg(&g_dinv[s]) * __ldg(&g_dinv[d]);
    float v = __ldg(hw + s * 40 + lane) * norm;
    asm volatile("red.global.add.f32 [%0], %1;" :: "l"(agg + d * 40 + lane), "f"(v) : "memory");
    if (lane < 8) {
        float v2 = __ldg(hw + s * 40 + 32 + lane) * norm;
        asm volatile("red.global.add.f32 [%0], %1;" :: "l"(agg + d * 40 + 32 + lane), "f"(v2) : "memory");
    }
}

// ---------------- batchnorm stats + finalize -------------------------------
__global__ __launch_bounds__(256) void k_bnstats(const float* __restrict__ h,
                                                 float* __restrict__ sums) {
    __shared__ float ss[256], sq[256];
    int tid = threadIdx.x;
    int c = tid & 127;
    int half = tid >> 7;
    int rbeg = blockIdx.x * 250;        // grid = 400, covers exactly 100000
    float s = 0.f, q = 0.f;
    for (int r = rbeg + half; r < rbeg + 250; r += 2) {
        float v = h[r * 128 + c];
        s += v;
        q = fmaf(v, v, q);
    }
    ss[tid] = s; sq[tid] = q;
    __syncthreads();
    if (half == 0) {
        atomicAdd(&sums[c],       ss[tid] + ss[tid + 128]);
        atomicAdd(&sums[128 + c], sq[tid] + sq[tid + 128]);
    }
}

__global__ void k_bnfinal(const float* __restrict__ sums,
                          const float* __restrict__ gamma, const float* __restrict__ beta,
                          float* __restrict__ sc, float* __restrict__ sh) {
    int c = threadIdx.x;                // 128 threads
    const float inv_n = 1.0f / (float)NNODES;
    float mean = sums[c] * inv_n;
    float var  = sums[128 + c] * inv_n - mean * mean;
    var = fmaxf(var, 0.f);
    float rstd = rsqrtf(var + 1e-5f);
    float a = gamma[c] * rstd;
    sc[c] = a;
    sh[c] = beta[c] - mean * a;
}

// ---------------- fused BN + ReLU + exact threefry dropout -----------------
__global__ __launch_bounds__(256) void k_bndrop(
    const float4* __restrict__ in, float4* __restrict__ out,
    const float* __restrict__ sc, const float* __restrict__ sh,
    int layer, int n4)
{
    int t = blockIdx.x * 256 + threadIdx.x;
    if (t >= n4) return;
    uint32_t k0 = g_keys[layer * 2 + 0];
    uint32_t k1 = g_keys[layer * 2 + 1];
    uint32_t k2 = k0 ^ k1 ^ 0x1BD11BDAu;

    int c = (t & 31) * 4;
    float4 v = in[t];
    float4 a = *(const float4*)(sc + c);
    float4 b = *(const float4*)(sh + c);

    float r0 = fmaxf(fmaf(v.x, a.x, b.x), 0.f);
    float r1 = fmaxf(fmaf(v.y, a.y, b.y), 0.f);
    float r2 = fmaxf(fmaf(v.z, a.z, b.z), 0.f);
    float r3 = fmaxf(fmaf(v.w, a.w, b.w), 0.f);

    uint32_t i0 = (uint32_t)t * 4u;
    uint32_t m0 = tf_bits_xor(k0, k1, k2, i0 + 0u);
    uint32_t m1 = tf_bits_xor(k0, k1, k2, i0 + 1u);
    uint32_t m2 = tf_bits_xor(k0, k1, k2, i0 + 2u);
    uint32_t m3 = tf_bits_xor(k0, k1, k2, i0 + 3u);

    // keep iff uniform < 0.5 iff bit31(bits)==0 ; kept values scaled by 1/(1-p)=2
    v.x = (m0 & 0x80000000u) ? 0.f : r0 + r0;
    v.y = (m1 & 0x80000000u) ? 0.f : r1 + r1;
    v.z = (m2 & 0x80000000u) ? 0.f : r2 + r2;
    v.w = (m3 & 0x80000000u) ? 0.f : r3 + r3;
    out[t] = v;
}

// ---------------- log_softmax over 40 cols (warp per row) ------------------
__global__ __launch_bounds__(256) void k_logsoftmax(const float* __restrict__ in,
                                                    float* __restrict__ out, int n) {
    int r = blockIdx.x * 8 + (threadIdx.x >> 5);
    if (r >= n) return;
    int lane = threadIdx.x & 31;
    float v0 = __ldg(in + r * 40 + lane);
    float v1 = (lane < 8) ? __ldg(in + r * 40 + 32 + lane) : -3.4e38f;
    float mx = fmaxf(v0, v1);
#pragma unroll
    for (int o = 16; o; o >>= 1) mx = fmaxf(mx, __shfl_xor_sync(0xffffffffu, mx, o));
    float s = expf(v0 - mx) + ((lane < 8) ? expf(v1 - mx) : 0.f);
#pragma unroll
    for (int o = 16; o; o >>= 1) s += __shfl_xor_sync(0xffffffffu, s, o);
    float l = mx + logf(s);
    out[r * 40 + lane] = v0 - l;
    if (lane < 8) out[r * 40 + 32 + lane] = v1 - l;
}

// ---------------- launch ---------------------------------------------------
extern "C" void kernel_launch(void* const* d_in, const int* in_sizes, int n_in,
                              void* d_out, int out_size) {
    const float* x   = (const float*)d_in[0];
    const int*   ei  = (const int*)  d_in[1];
    const float* W1  = (const float*)d_in[2];
    const float* b1  = (const float*)d_in[3];
    const float* g1  = (const float*)d_in[4];
    const float* be1 = (const float*)d_in[5];
    const float* W2  = (const float*)d_in[6];
    const float* b2  = (const float*)d_in[7];
    const float* g2  = (const float*)d_in[8];
    const float* be2 = (const float*)d_in[9];
    const float* W3  = (const float*)d_in[10];
    const float* b3  = (const float*)d_in[11];
    int E = in_sizes[1] / 2;
    const int* src = ei;
    const int* dst = ei + E;
    float* out = (float*)d_out;

    void *pA, *pB, *pH3, *pG3, *pS, *pSc, *pSh;
    cudaGetSymbolAddress(&pA,  g_bufA);
    cudaGetSymbolAddress(&pB,  g_bufB);
    cudaGetSymbolAddress(&pH3, g_hw3);
    cudaGetSymbolAddress(&pG3, g_agg3);
    cudaGetSymbolAddress(&pS,  g_sums);
    cudaGetSymbolAddress(&pSc, g_scale);
    cudaGetSymbolAddress(&pSh, g_shift);
    float4* bufA = (float4*)pA;
    float4* bufB = (float4*)pB;
    float4* hw3  = (float4*)pH3;
    float4* agg3 = (float4*)pG3;
    float* sums  = (float*)pS;
    float* scale = (float*)pSc;
    float* shift = (float*)pSh;

    const int n4_128 = NNODES * 32;     // 3,200,000 float4
    const int n4_40  = NNODES * 10;     // 1,000,000 float4
    const int GB128  = n4_128 / 256;    // 12500
    const int GB40   = (n4_40 + 255) / 256;
    const int GN     = (NNODES + 255) / 256;
    const int GE     = (E + 255) / 256;
    const int GEW    = (E + 7) / 8;     // warp per edge
    const int GM     = (NNODES + 127) / 128;

    k_zero<<<GN, 256>>>();
    k_degree<<<GE, 256>>>(dst, E);
    k_dinv<<<GN, 256>>>();
    k_keys<<<1, 32>>>();

    // ---- layer 1 ----
    sgemm_k128<<<GM, 256>>>(x, W1, (float*)bufA, NNODES, 128);
    k_init128<<<GB128, 256>>>(bufA, bufB, b1, n4_128);
    scatter128<<<GEW, 256>>>(bufA, bufB, src, dst, E);
    k_bnstats<<<400, 256>>>((const float*)bufB, sums);
    k_bnfinal<<<1, 128>>>(sums, g1, be1, scale, shift);
    k_bndrop<<<GB128, 256>>>(bufB, bufA, scale, shift, 0, n4_128);

    // ---- layer 2 ----
    sgemm_k128<<<GM, 256>>>((const float*)bufA, W2, (float*)bufB, NNODES, 128);
    k_init128<<<GB128, 256>>>(bufB, bufA, b2, n4_128);
    scatter128<<<GEW, 256>>>(bufB, bufA, src, dst, E);
    k_bnstats<<<400, 256>>>((const float*)bufA, sums + 256);
    k_bnfinal<<<1, 128>>>(sums + 256, g2, be2, scale + 128, shift + 128);
    k_bndrop<<<GB128, 256>>>(bufA, bufB, scale + 128, shift + 128, 1, n4_128);

    // ---- layer 3 + log_softmax ----
    sgemm_k128<<<GM, 256>>>((const float*)bufB, W3, (float*)hw3, NNODES, 40);
    k_init40<<<GB40, 256>>>(hw3, agg3, b3, n4_40);
    scatter40<<<GEW, 256>>>((const float*)hw3, (float*)agg3, src, dst, E);
    k_logsoftmax<<<(NNODES + 7) / 8, 256>>>((const float*)agg3, out, NNODES);
}

// round 5
// speedup vs baseline: 1.5770x; 1.5770x over previous
#include <cuda_runtime.h>
#include <cstdint>

#define NNODES 100000
#define MAXE   1000000

// ---------------- scratch (static __device__ globals; no allocation) -------
__device__ __align__(16) float4 g_bufA[NNODES * 32];   // 100000 x 128 floats
__device__ __align__(16) float4 g_bufB[NNODES * 32];   // 100000 x 128 floats
__device__ __align__(16) float4 g_hw3 [NNODES * 10];   // 100000 x 40 floats
__device__ __align__(16) float4 g_agg3[NNODES * 10];   // 100000 x 40 floats
__device__ float g_dinv[NNODES];
__device__ int   g_icnt[NNODES];        // degree histogram
__device__ int   g_fc  [NNODES];        // fill counters
__device__ int   g_rs  [NNODES + 1];    // CSR row starts (by dst)
__device__ int   g_perm[MAXE];          // src node per CSR slot
__device__ int   g_bsum[512];
__device__ int   g_boff[512];
__device__ float g_sums[512];           // 2 layers x (sum[128], sumsq[128])
__device__ __align__(16) float g_scale[256];
__device__ __align__(16) float g_shift[256];
__device__ unsigned g_keys[4];          // dk0.(x,y), dk1.(x,y)

#define SCAN_BLOCKS 391                 // ceil(100000/256)

// ---------------- threefry2x32 (JAX-exact, 20 rounds) ----------------------
__device__ __forceinline__ void tf_round(uint32_t &x0, uint32_t &x1, int r) {
    x0 += x1;
    x1 = __funnelshift_l(x1, x1, r);
    x1 ^= x0;
}

__device__ __forceinline__ uint2 tf_full(uint32_t k0, uint32_t k1, uint32_t x0, uint32_t x1) {
    uint32_t k2 = k0 ^ k1 ^ 0x1BD11BDAu;
    x0 += k0; x1 += k1;
    tf_round(x0,x1,13); tf_round(x0,x1,15); tf_round(x0,x1,26); tf_round(x0,x1,6);
    x0 += k1; x1 += k2 + 1u;
    tf_round(x0,x1,17); tf_round(x0,x1,29); tf_round(x0,x1,16); tf_round(x0,x1,24);
    x0 += k2; x1 += k0 + 2u;
    tf_round(x0,x1,13); tf_round(x0,x1,15); tf_round(x0,x1,26); tf_round(x0,x1,6);
    x0 += k0; x1 += k1 + 3u;
    tf_round(x0,x1,17); tf_round(x0,x1,29); tf_round(x0,x1,16); tf_round(x0,x1,24);
    x0 += k1; x1 += k2 + 4u;
    tf_round(x0,x1,13); tf_round(x0,x1,15); tf_round(x0,x1,26); tf_round(x0,x1,6);
    x0 += k2; x1 += k0 + 5u;
    return make_uint2(x0, x1);
}

// JAX partitionable random_bits(32): bits(i) = bits1 ^ bits2 of threefry(key,(0,i))
__device__ __forceinline__ uint32_t tf_bits_xor(uint32_t k0, uint32_t k1, uint32_t k2, uint32_t ctr) {
    uint32_t x0 = k0;
    uint32_t x1 = ctr + k1;
    tf_round(x0,x1,13); tf_round(x0,x1,15); tf_round(x0,x1,26); tf_round(x0,x1,6);
    x0 += k1; x1 += k2 + 1u;
    tf_round(x0,x1,17); tf_round(x0,x1,29); tf_round(x0,x1,16); tf_round(x0,x1,24);
    x0 += k2; x1 += k0 + 2u;
    tf_round(x0,x1,13); tf_round(x0,x1,15); tf_round(x0,x1,26); tf_round(x0,x1,6);
    x0 += k0; x1 += k1 + 3u;
    tf_round(x0,x1,17); tf_round(x0,x1,29); tf_round(x0,x1,16); tf_round(x0,x1,24);
    x0 += k1; x1 += k2 + 4u;
    tf_round(x0,x1,13); tf_round(x0,x1,15); tf_round(x0,x1,26); tf_round(x0,x1,6);
    x0 += k2; x1 += k0 + 5u;
    return x0 ^ x1;
}

__global__ void k_keys() {
    if (threadIdx.x == 0) {
        uint2 a = tf_full(0u, 42u, 0u, 0u);
        uint2 b = tf_full(0u, 42u, 0u, 1u);
        g_keys[0] = a.x; g_keys[1] = a.y;
        g_keys[2] = b.x; g_keys[3] = b.y;
    }
}

// ---------------- graph preprocessing --------------------------------------
__global__ void k_zero() {
    int i = blockIdx.x * 256 + threadIdx.x;
    if (i < NNODES) { g_icnt[i] = 0; g_fc[i] = 0; }
    if (i < 512)    g_sums[i] = 0.f;
}

__global__ void k_degree(const int* __restrict__ dst, int E) {
    int e = blockIdx.x * 256 + threadIdx.x;
    if (e < E) atomicAdd(&g_icnt[dst[e]], 1);
}

__global__ void k_dinv() {
    int i = blockIdx.x * 256 + threadIdx.x;
    if (i < NNODES) g_dinv[i] = rsqrtf((float)g_icnt[i] + 1.0f);
}

// exclusive scan of g_icnt -> g_rs, 3-phase
__global__ __launch_bounds__(256) void k_scan_local() {
    __shared__ int s[256];
    int t = threadIdx.x;
    int i = blockIdx.x * 256 + t;
    int v = (i < NNODES) ? g_icnt[i] : 0;
    s[t] = v;
    __syncthreads();
#pragma unroll
    for (int off = 1; off < 256; off <<= 1) {
        int add = (t >= off) ? s[t - off] : 0;
        __syncthreads();
        s[t] += add;
        __syncthreads();
    }
    if (i < NNODES) g_rs[i] = s[t] - v;       // exclusive, block-local
    if (t == 255) g_bsum[blockIdx.x] = s[255];
}

__global__ __launch_bounds__(512) void k_scan_block() {
    __shared__ int s[512];
    int t = threadIdx.x;
    int v = (t < SCAN_BLOCKS) ? g_bsum[t] : 0;
    s[t] = v;
    __syncthreads();
#pragma unroll
    for (int off = 1; off < 512; off <<= 1) {
        int add = (t >= off) ? s[t - off] : 0;
        __syncthreads();
        s[t] += add;
        __syncthreads();
    }
    g_boff[t] = s[t] - v;                     // exclusive block offsets
}

__global__ void k_scan_add(int E) {
    int i = blockIdx.x * 256 + threadIdx.x;
    if (i < NNODES) g_rs[i] += g_boff[blockIdx.x];
    if (i == NNODES) g_rs[NNODES] = E;
}

__global__ void k_fill(const int* __restrict__ src, const int* __restrict__ dst, int E) {
    int e = blockIdx.x * 256 + threadIdx.x;
    if (e >= E) return;
    int d = dst[e];
    int pos = g_rs[d] + atomicAdd(&g_fc[d], 1);
    g_perm[pos] = src[e];
}

// ---------------- SGEMM: C[M x 128] = A[M x 128] * B[128 x 128] ------------
__global__ __launch_bounds__(256) void sgemm_k128(
    const float* __restrict__ A, const float* __restrict__ B,
    float* __restrict__ C, int M)
{
    __shared__ __align__(16) float As[8][128];   // [k][row]
    __shared__ __align__(16) float Bs[8][128];   // [k][col]
    int tid  = threadIdx.x;
    int row0 = blockIdx.x * 128;
    int tx = tid & 15, ty = tid >> 4;

    float acc[8][8];
#pragma unroll
    for (int i = 0; i < 8; i++)
#pragma unroll
        for (int j = 0; j < 8; j++) acc[i][j] = 0.f;

    int a_row = tid >> 1;
    int a_c4  = (tid & 1) * 4;
    int b_row = tid >> 5;
    int b_c4  = (tid & 31) * 4;

    for (int k0 = 0; k0 < 128; k0 += 8) {
        float4 av = make_float4(0.f, 0.f, 0.f, 0.f);
        int gr = row0 + a_row;
        if (gr < M) av = *(const float4*)(A + gr * 128 + k0 + a_c4);
        As[a_c4 + 0][a_row] = av.x;
        As[a_c4 + 1][a_row] = av.y;
        As[a_c4 + 2][a_row] = av.z;
        As[a_c4 + 3][a_row] = av.w;
        *(float4*)&Bs[b_row][b_c4] = *(const float4*)(B + (k0 + b_row) * 128 + b_c4);
        __syncthreads();

#pragma unroll
        for (int k = 0; k < 8; k++) {
            float af[8], bf[8];
            *(float4*)&af[0] = *(const float4*)&As[k][ty * 8];
            *(float4*)&af[4] = *(const float4*)&As[k][ty * 8 + 4];
            *(float4*)&bf[0] = *(const float4*)&Bs[k][tx * 8];
            *(float4*)&bf[4] = *(const float4*)&Bs[k][tx * 8 + 4];
#pragma unroll
            for (int i = 0; i < 8; i++)
#pragma unroll
                for (int j = 0; j < 8; j++)
                    acc[i][j] = fmaf(af[i], bf[j], acc[i][j]);
        }
        __syncthreads();
    }

#pragma unroll
    for (int i = 0; i < 8; i++) {
        int r = row0 + ty * 8 + i;
        if (r < M) {
            *(float4*)(C + r * 128 + tx * 8)     = make_float4(acc[i][0], acc[i][1], acc[i][2], acc[i][3]);
            *(float4*)(C + r * 128 + tx * 8 + 4) = make_float4(acc[i][4], acc[i][5], acc[i][6], acc[i][7]);
        }
    }
}

// ---------------- SGEMM narrow: C[M x 40] = A[M x 128] * B[128 x 40] -------
// 128x64 tile (cols 40..63 padded zero), acc 8x4 per thread -> half the FMAs
__global__ __launch_bounds__(256) void sgemm_n64(
    const float* __restrict__ A, const float* __restrict__ B,
    float* __restrict__ C, int M, int NC)
{
    __shared__ __align__(16) float As[8][128];
    __shared__ __align__(16) float Bs[8][64];
    int tid  = threadIdx.x;
    int row0 = blockIdx.x * 128;
    int tx = tid & 15, ty = tid >> 4;       // tx: 16 col-groups of 4, ty: 16 row-groups of 8

    float acc[8][4];
#pragma unroll
    for (int i = 0; i < 8; i++)
#pragma unroll
        for (int j = 0; j < 4; j++) acc[i][j] = 0.f;

    int a_row = tid >> 1;
    int a_c4  = (tid & 1) * 4;

    for (int k0 = 0; k0 < 128; k0 += 8) {
        float4 av = make_float4(0.f, 0.f, 0.f, 0.f);
        int gr = row0 + a_row;
        if (gr < M) av = *(const float4*)(A + gr * 128 + k0 + a_c4);
        As[a_c4 + 0][a_row] = av.x;
        As[a_c4 + 1][a_row] = av.y;
        As[a_c4 + 2][a_row] = av.z;
        As[a_c4 + 3][a_row] = av.w;
        // B tile: 8 rows x 64 cols = 512 entries, 2 per thread
#pragma unroll
        for (int u = 0; u < 2; u++) {
            int idx = tid * 2 + u;
            int bk = idx >> 6, bc = idx & 63;
            Bs[bk][bc] = (bc < NC) ? B[(k0 + bk) * NC + bc] : 0.f;
        }
        __syncthreads();

#pragma unroll
        for (int k = 0; k < 8; k++) {
            float af[8], bf[4];
            *(float4*)&af[0] = *(const float4*)&As[k][ty * 8];
            *(float4*)&af[4] = *(const float4*)&As[k][ty * 8 + 4];
            *(float4*)&bf[0] = *(const float4*)&Bs[k][tx * 4];
#pragma unroll
            for (int i = 0; i < 8; i++)
#pragma unroll
                for (int j = 0; j < 4; j++)
                    acc[i][j] = fmaf(af[i], bf[j], acc[i][j]);
        }
        __syncthreads();
    }

#pragma unroll
    for (int i = 0; i < 8; i++) {
        int r = row0 + ty * 8 + i;
        if (r < M) {
#pragma unroll
            for (int j = 0; j < 4; j++) {
                int c = tx * 4 + j;
                if (c < NC) C[r * NC + c] = acc[i][j];
            }
        }
    }
}

// ---------------- CSR SpMM (no atomics): agg = Anorm*hw + self + bias ------
__global__ __launch_bounds__(256) void spmm128(
    const float4* __restrict__ hw, float4* __restrict__ agg,
    const float* __restrict__ bias)
{
    int row = blockIdx.x * 8 + (threadIdx.x >> 5);
    if (row >= NNODES) return;
    int lane = threadIdx.x & 31;
    int beg = __ldg(&g_rs[row]);
    int end = __ldg(&g_rs[row + 1]);
    float di = g_dinv[row];
    float di2 = di * di;

    float4 self = __ldg(hw + row * 32 + lane);
    float4 b = ((const float4*)bias)[lane];
    float4 acc  = make_float4(fmaf(self.x, di2, b.x), fmaf(self.y, di2, b.y),
                              fmaf(self.z, di2, b.z), fmaf(self.w, di2, b.w));
    float4 acc2 = make_float4(0.f, 0.f, 0.f, 0.f);

    int j = beg;
    for (; j + 1 < end; j += 2) {
        int s0 = __ldg(&g_perm[j]);
        int s1 = __ldg(&g_perm[j + 1]);
        float n0 = __ldg(&g_dinv[s0]) * di;
        float n1 = __ldg(&g_dinv[s1]) * di;
        float4 v0 = __ldg(hw + s0 * 32 + lane);
        float4 v1 = __ldg(hw + s1 * 32 + lane);
        acc.x  = fmaf(v0.x, n0, acc.x);  acc.y  = fmaf(v0.y, n0, acc.y);
        acc.z  = fmaf(v0.z, n0, acc.z);  acc.w  = fmaf(v0.w, n0, acc.w);
        acc2.x = fmaf(v1.x, n1, acc2.x); acc2.y = fmaf(v1.y, n1, acc2.y);
        acc2.z = fmaf(v1.z, n1, acc2.z); acc2.w = fmaf(v1.w, n1, acc2.w);
    }
    if (j < end) {
        int s0 = __ldg(&g_perm[j]);
        float n0 = __ldg(&g_dinv[s0]) * di;
        float4 v0 = __ldg(hw + s0 * 32 + lane);
        acc.x = fmaf(v0.x, n0, acc.x); acc.y = fmaf(v0.y, n0, acc.y);
        acc.z = fmaf(v0.z, n0, acc.z); acc.w = fmaf(v0.w, n0, acc.w);
    }
    agg[row * 32 + lane] = make_float4(acc.x + acc2.x, acc.y + acc2.y,
                                       acc.z + acc2.z, acc.w + acc2.w);
}

__global__ __launch_bounds__(256) void spmm40(
    const float4* __restrict__ hw, float4* __restrict__ agg,
    const float* __restrict__ bias)
{
    int row = blockIdx.x * 8 + (threadIdx.x >> 5);
    if (row >= NNODES) return;
    int lane = threadIdx.x & 31;
    if (lane >= 10) return;
    int beg = __ldg(&g_rs[row]);
    int end = __ldg(&g_rs[row + 1]);
    float di = g_dinv[row];
    float di2 = di * di;

    float4 self = __ldg(hw + row * 10 + lane);
    float4 b = ((const float4*)bias)[lane];
    float4 acc = make_float4(fmaf(self.x, di2, b.x), fmaf(self.y, di2, b.y),
                             fmaf(self.z, di2, b.z), fmaf(self.w, di2, b.w));
    for (int j = beg; j < end; j++) {
        int s = __ldg(&g_perm[j]);
        float n = __ldg(&g_dinv[s]) * di;
        float4 v = __ldg(hw + s * 10 + lane);
        acc.x = fmaf(v.x, n, acc.x); acc.y = fmaf(v.y, n, acc.y);
        acc.z = fmaf(v.z, n, acc.z); acc.w = fmaf(v.w, n, acc.w);
    }
    agg[row * 10 + lane] = acc;
}

// ---------------- batchnorm stats + finalize -------------------------------
__global__ __launch_bounds__(256) void k_bnstats(const float* __restrict__ h,
                                                 float* __restrict__ sums) {
    __shared__ float ss[256], sq[256];
    int tid = threadIdx.x;
    int c = tid & 127;
    int half = tid >> 7;
    int rbeg = blockIdx.x * 250;
    float s = 0.f, q = 0.f;
    for (int r = rbeg + half; r < rbeg + 250; r += 2) {
        float v = h[r * 128 + c];
        s += v;
        q = fmaf(v, v, q);
    }
    ss[tid] = s; sq[tid] = q;
    __syncthreads();
    if (half == 0) {
        atomicAdd(&sums[c],       ss[tid] + ss[tid + 128]);
        atomicAdd(&sums[128 + c], sq[tid] + sq[tid + 128]);
    }
}

__global__ void k_bnfinal(const float* __restrict__ sums,
                          const float* __restrict__ gamma, const float* __restrict__ beta,
                          float* __restrict__ sc, float* __restrict__ sh) {
    int c = threadIdx.x;
    const float inv_n = 1.0f / (float)NNODES;
    float mean = sums[c] * inv_n;
    float var  = sums[128 + c] * inv_n - mean * mean;
    var = fmaxf(var, 0.f);
    float rstd = rsqrtf(var + 1e-5f);
    float a = gamma[c] * rstd;
    sc[c] = a;
    sh[c] = beta[c] - mean * a;
}

// ---------------- fused BN + ReLU + exact threefry dropout -----------------
__global__ __launch_bounds__(256) void k_bndrop(
    const float4* __restrict__ in, float4* __restrict__ out,
    const float* __restrict__ sc, const float* __restrict__ sh,
    int layer, int n4)
{
    int t = blockIdx.x * 256 + threadIdx.x;
    if (t >= n4) return;
    uint32_t k0 = g_keys[layer * 2 + 0];
    uint32_t k1 = g_keys[layer * 2 + 1];
    uint32_t k2 = k0 ^ k1 ^ 0x1BD11BDAu;

    int c = (t & 31) * 4;
    float4 v = in[t];
    float4 a = *(const float4*)(sc + c);
    float4 b = *(const float4*)(sh + c);

    float r0 = fmaxf(fmaf(v.x, a.x, b.x), 0.f);
    float r1 = fmaxf(fmaf(v.y, a.y, b.y), 0.f);
    float r2 = fmaxf(fmaf(v.z, a.z, b.z), 0.f);
    float r3 = fmaxf(fmaf(v.w, a.w, b.w), 0.f);

    uint32_t i0 = (uint32_t)t * 4u;
    uint32_t m0 = tf_bits_xor(k0, k1, k2, i0 + 0u);
    uint32_t m1 = tf_bits_xor(k0, k1, k2, i0 + 1u);
    uint32_t m2 = tf_bits_xor(k0, k1, k2, i0 + 2u);
    uint32_t m3 = tf_bits_xor(k0, k1, k2, i0 + 3u);

    v.x = (m0 & 0x80000000u) ? 0.f : r0 + r0;
    v.y = (m1 & 0x80000000u) ? 0.f : r1 + r1;
    v.z = (m2 & 0x80000000u) ? 0.f : r2 + r2;
    v.w = (m3 & 0x80000000u) ? 0.f : r3 + r3;
    out[t] = v;
}

// ---------------- log_softmax over 40 cols (warp per row) ------------------
__global__ __launch_bounds__(256) void k_logsoftmax(const float* __restrict__ in,
                                                    float* __restrict__ out, int n) {
    int r = blockIdx.x * 8 + (threadIdx.x >> 5);
    if (r >= n) return;
    int lane = threadIdx.x & 31;
    float v0 = __ldg(in + r * 40 + lane);
    float v1 = (lane < 8) ? __ldg(in + r * 40 + 32 + lane) : -3.4e38f;
    float mx = fmaxf(v0, v1);
#pragma unroll
    for (int o = 16; o; o >>= 1) mx = fmaxf(mx, __shfl_xor_sync(0xffffffffu, mx, o));
    float s = expf(v0 - mx) + ((lane < 8) ? expf(v1 - mx) : 0.f);
#pragma unroll
    for (int o = 16; o; o >>= 1) s += __shfl_xor_sync(0xffffffffu, s, o);
    float l = mx + logf(s);
    out[r * 40 + lane] = v0 - l;
    if (lane < 8) out[r * 40 + 32 + lane] = v1 - l;
}

// ---------------- launch ---------------------------------------------------
extern "C" void kernel_launch(void* const* d_in, const int* in_sizes, int n_in,
                              void* d_out, int out_size) {
    const float* x   = (const float*)d_in[0];
    const int*   ei  = (const int*)  d_in[1];
    const float* W1  = (const float*)d_in[2];
    const float* b1  = (const float*)d_in[3];
    const float* g1  = (const float*)d_in[4];
    const float* be1 = (const float*)d_in[5];
    const float* W2  = (const float*)d_in[6];
    const float* b2  = (const float*)d_in[7];
    const float* g2  = (const float*)d_in[8];
    const float* be2 = (const float*)d_in[9];
    const float* W3  = (const float*)d_in[10];
    const float* b3  = (const float*)d_in[11];
    int E = in_sizes[1] / 2;
    const int* src = ei;
    const int* dst = ei + E;
    float* out = (float*)d_out;

    void *pA, *pB, *pH3, *pG3, *pS, *pSc, *pSh;
    cudaGetSymbolAddress(&pA,  g_bufA);
    cudaGetSymbolAddress(&pB,  g_bufB);
    cudaGetSymbolAddress(&pH3, g_hw3);
    cudaGetSymbolAddress(&pG3, g_agg3);
    cudaGetSymbolAddress(&pS,  g_sums);
    cudaGetSymbolAddress(&pSc, g_scale);
    cudaGetSymbolAddress(&pSh, g_shift);
    float4* bufA = (float4*)pA;
    float4* bufB = (float4*)pB;
    float4* hw3  = (float4*)pH3;
    float4* agg3 = (float4*)pG3;
    float* sums  = (float*)pS;
    float* scale = (float*)pSc;
    float* shift = (float*)pSh;

    const int n4_128 = NNODES * 32;
    const int GB128  = n4_128 / 256;
    const int GN     = (NNODES + 255) / 256;
    const int GE     = (E + 255) / 256;
    const int GROW   = (NNODES + 7) / 8;     // warp per row
    const int GM     = (NNODES + 127) / 128;

    // preprocessing (sgemm1 placed early in hopes ncu -s5 captures it)
    k_zero  <<<GN, 256>>>();
    k_degree<<<GE, 256>>>(dst, E);
    k_keys  <<<1, 32>>>();
    sgemm_k128<<<GM, 256>>>(x, W1, (float*)bufA, NNODES);
    k_dinv      <<<GN, 256>>>();
    k_scan_local<<<SCAN_BLOCKS, 256>>>();
    k_scan_block<<<1, 512>>>();
    k_scan_add  <<<SCAN_BLOCKS, 256>>>(E);
    k_fill      <<<GE, 256>>>(src, dst, E);

    // ---- layer 1 ----
    spmm128 <<<GROW, 256>>>(bufA, bufB, b1);
    k_bnstats<<<400, 256>>>((const float*)bufB, sums);
    k_bnfinal<<<1, 128>>>(sums, g1, be1, scale, shift);
    k_bndrop<<<GB128, 256>>>(bufB, bufA, scale, shift, 0, n4_128);

    // ---- layer 2 ----
    sgemm_k128<<<GM, 256>>>((const float*)bufA, W2, (float*)bufB, NNODES);
    spmm128 <<<GROW, 256>>>(bufB, bufA, b2);
    k_bnstats<<<400, 256>>>((const float*)bufA, sums + 256);
    k_bnfinal<<<1, 128>>>(sums + 256, g2, be2, scale + 128, shift + 128);
    k_bndrop<<<GB128, 256>>>(bufA, bufB, scale + 128, shift + 128, 1, n4_128);

    // ---- layer 3 + log_softmax ----
    sgemm_n64<<<GM, 256>>>((const float*)bufB, W3, (float*)hw3, NNODES, 40);
    spmm40  <<<GROW, 256>>>(hw3, agg3, b3);
    k_logsoftmax<<<GROW, 256>>>((const float*)agg3, out, NNODES);
}